// round 3
// baseline (speedup 1.0000x reference)
#include <cuda_runtime.h>
#include <math.h>
#include <stdint.h>

typedef unsigned long long u64;

#define GMAX 10240
#define NWARP 16
#define BLOCK 512
#define RPB 128   // rows per block (4 per lane: 2 packed pairs)

// Precomputed SH table, duplicated-pair SoA:
// plane0={dup(Y0),dup(Y1)} plane1={dup(Y2),dup(Y3)} plane2={dup(Y4),dup(Y5)}
// plane3={dup(Y6),dup(Y7)} plane4={dup(Y8),dup(gx)} plane5={dup(gy),dup(gz)}
__device__ ulonglong2 g_dupP[6][GMAX];

__device__ __forceinline__ u64 dup2(float f) {
    u64 r; asm("mov.b64 %0, {%1, %1};" : "=l"(r) : "f"(f)); return r;
}
__device__ __forceinline__ u64 pk2(float lo, float hi) {
    u64 r; asm("mov.b64 %0, {%1, %2};" : "=l"(r) : "f"(lo), "f"(hi)); return r;
}
__device__ __forceinline__ void upk2(u64 v, float& lo, float& hi) {
    asm("mov.b64 {%0, %1}, %2;" : "=f"(lo), "=f"(hi) : "l"(v));
}
__device__ __forceinline__ u64 fma2(u64 a, u64 b, u64 c) {
    u64 r; asm("fma.rn.f32x2 %0, %1, %2, %3;" : "=l"(r) : "l"(a), "l"(b), "l"(c)); return r;
}
__device__ __forceinline__ u64 mul2(u64 a, u64 b) {
    u64 r; asm("mul.rn.f32x2 %0, %1, %2;" : "=l"(r) : "l"(a), "l"(b)); return r;
}

// 9-term SH dot — SINGLE sequential chain. This exact rounding order matched
// the reference argmax selection in R1 (rel_err 4.8e-8); do NOT re-associate.
__device__ __forceinline__ u64 sig9(const u64* C,
                                    const ulonglong2 v0, const ulonglong2 v1,
                                    const ulonglong2 v2, const ulonglong2 v3,
                                    const u64 v4x) {
    u64 acc = mul2(C[0], v0.x);
    acc = fma2(C[1], v0.y, acc);
    acc = fma2(C[2], v1.x, acc);
    acc = fma2(C[3], v1.y, acc);
    acc = fma2(C[4], v2.x, acc);
    acc = fma2(C[5], v2.y, acc);
    acc = fma2(C[6], v3.x, acc);
    acc = fma2(C[7], v3.y, acc);
    acc = fma2(C[8], v4x, acc);
    return acc;
}

__device__ __forceinline__ u64 dot3(u64 zx, u64 zy, u64 zz, u64 gx, u64 gy, u64 gz) {
    u64 d = mul2(zx, gx);
    d = fma2(zy, gy, d);
    return fma2(zz, gz, d);
}

__device__ __forceinline__ void amax(u64 s, int gg,
                                     float& v0, int& i0, float& v1, int& i1) {
    float a, b; upk2(s, a, b);
    if (a > v0) { v0 = a; i0 = gg; }
    if (b > v1) { v1 = b; i1 = gg; }
}

__device__ __forceinline__ void amaxm(u64 s, u64 d, int gg,
                                      float& v0, int& i0, float& v1, int& i1) {
    float a, b, da, db; upk2(s, a, b); upk2(d, da, db);
    if (fabsf(da) < 0.2f && a > v0) { v0 = a; i0 = gg; }
    if (fabsf(db) < 0.2f && b > v1) { v1 = b; i1 = gg; }
}

// ---------------------------------------------------------------------------
// Kernel 1: precompute l=4 SH basis per grid dir, dup-packed SoA planes.
// ---------------------------------------------------------------------------
__global__ void sh_precompute_kernel(const float* __restrict__ grid, int G) {
    int g = blockIdx.x * blockDim.x + threadIdx.x;
    if (g >= G) return;
    float gx = grid[3 * g + 0], gy = grid[3 * g + 1], gz = grid[3 * g + 2];
    float n = sqrtf(gx * gx + gy * gy + gz * gz);
    float inv = 1.0f / fmaxf(n, 1e-12f);
    float x = gx * inv, y = gy * inv, z = gz * inv;
    float x2 = x * x, y2 = y * y, z2 = z * z;
    float Y0 = 2.5033429417967046f * (x * y * (x2 - y2));
    float Y1 = 1.7701307697799304f * (y * z * (3.0f * x2 - y2));
    float Y2 = 0.9461746957575601f * (x * y * (7.0f * z2 - 1.0f));
    float Y3 = 0.6690465435572892f * (y * z * (7.0f * z2 - 3.0f));
    float Y4c = 0.10578554691520431f * (35.0f * z2 * z2 - 30.0f * z2 + 3.0f);
    float Y5 = 0.6690465435572892f * (x * z * (7.0f * z2 - 3.0f));
    float Y6 = 0.47308734787878004f * ((x2 - y2) * (7.0f * z2 - 1.0f));
    float Y7 = 1.7701307697799304f * (x * z * (x2 - y2));
    float Y8 = 0.6258357354491761f * (x2 * x2 - 6.0f * x2 * y2 + y2 * y2);
    g_dupP[0][g] = make_ulonglong2(dup2(Y0), dup2(Y1));
    g_dupP[1][g] = make_ulonglong2(dup2(Y2), dup2(Y3));
    g_dupP[2][g] = make_ulonglong2(dup2(Y4c), dup2(Y5));
    g_dupP[3][g] = make_ulonglong2(dup2(Y6), dup2(Y7));
    g_dupP[4][g] = make_ulonglong2(dup2(Y8), dup2(gx));
    g_dupP[5][g] = make_ulonglong2(dup2(gy), dup2(gz));
}

// ---------------------------------------------------------------------------
// Kernel 2: fused two-pass argmax + quaternion epilogue.
// 512 threads = 16 warps, 128 rows/block (4 rows per lane as 2 f32x2 pairs).
// All lanes of a warp broadcast-read the same table entry via LDG (L1/L2 hit).
// 8 independent FMA chains per loop iteration hide the 9-deep chain latency.
// ---------------------------------------------------------------------------
__global__ __launch_bounds__(BLOCK) void decoder_kernel(
    const float* __restrict__ f0,
    const float* __restrict__ f4,
    const float* __restrict__ grid,
    float* __restrict__ out,
    int B, int G)
{
    __shared__ float s_pv[NWARP][RPB];
    __shared__ int s_pidx[NWARP][RPB];
    __shared__ float s_z[RPB][3];

    const int tid = threadIdx.x;
    const int lane = tid & 31;
    const int wid = tid >> 5;
    const int rowbase = blockIdx.x * RPB;
    const float NEG_INF = __int_as_float(0xff800000);

    // row ids: pair F -> rows rowbase+2*lane, +1 ; pair H -> +64
    const int rF = rowbase + 2 * lane;
    const int rH = rF + 64;

    u64 F[9], H[9];
#pragma unroll
    for (int i = 0; i < 9; i++) {
        float a = (rF < B)     ? f4[rF * 9 + i]       : 0.0f;
        float b = (rF + 1 < B) ? f4[(rF + 1) * 9 + i] : 0.0f;
        float c = (rH < B)     ? f4[rH * 9 + i]       : 0.0f;
        float d = (rH + 1 < B) ? f4[(rH + 1) * 9 + i] : 0.0f;
        F[i] = pk2(a, b);
        H[i] = pk2(c, d);
    }

    const ulonglong2* __restrict__ P0 = g_dupP[0];
    const ulonglong2* __restrict__ P1 = g_dupP[1];
    const ulonglong2* __restrict__ P2 = g_dupP[2];
    const ulonglong2* __restrict__ P3 = g_dupP[3];
    const ulonglong2* __restrict__ P4 = g_dupP[4];
    const ulonglong2* __restrict__ P5 = g_dupP[5];

    float bv0 = NEG_INF, bv1 = NEG_INF, bv2 = NEG_INF, bv3 = NEG_INF;
    int bi0 = 0, bi1 = 0, bi2 = 0, bi3 = 0;

    // ------------------- pass 1: argmax of signal -> z axis -----------------
    int g = wid;
    for (; g + NWARP < G; g += 2 * NWARP) {
        const int g2 = g + NWARP;
        const ulonglong2 a0 = P0[g],  a1 = P1[g],  a2 = P2[g],  a3 = P3[g],  a4 = P4[g];
        const ulonglong2 b0 = P0[g2], b1 = P1[g2], b2 = P2[g2], b3 = P3[g2], b4 = P4[g2];
        u64 sFa = sig9(F, a0, a1, a2, a3, a4.x);
        u64 sHa = sig9(H, a0, a1, a2, a3, a4.x);
        u64 sFb = sig9(F, b0, b1, b2, b3, b4.x);
        u64 sHb = sig9(H, b0, b1, b2, b3, b4.x);
        amax(sFa, g,  bv0, bi0, bv1, bi1);
        amax(sHa, g,  bv2, bi2, bv3, bi3);
        amax(sFb, g2, bv0, bi0, bv1, bi1);
        amax(sHb, g2, bv2, bi2, bv3, bi3);
    }
    if (g < G) {
        const ulonglong2 a0 = P0[g], a1 = P1[g], a2 = P2[g], a3 = P3[g], a4 = P4[g];
        u64 sFa = sig9(F, a0, a1, a2, a3, a4.x);
        u64 sHa = sig9(H, a0, a1, a2, a3, a4.x);
        amax(sFa, g, bv0, bi0, bv1, bi1);
        amax(sHa, g, bv2, bi2, bv3, bi3);
    }

    s_pv[wid][2 * lane]      = bv0; s_pidx[wid][2 * lane]      = bi0;
    s_pv[wid][2 * lane + 1]  = bv1; s_pidx[wid][2 * lane + 1]  = bi1;
    s_pv[wid][64 + 2 * lane] = bv2; s_pidx[wid][64 + 2 * lane] = bi2;
    s_pv[wid][65 + 2 * lane] = bv3; s_pidx[wid][65 + 2 * lane] = bi3;
    __syncthreads();
    if (tid < RPB) {
        float v = s_pv[0][tid]; int idx = s_pidx[0][tid];
#pragma unroll
        for (int w = 1; w < NWARP; w++) {
            float ov = s_pv[w][tid]; int oi = s_pidx[w][tid];
            if (ov > v || (ov == v && oi < idx)) { v = ov; idx = oi; }
        }
        s_z[tid][0] = grid[3 * idx + 0];
        s_z[tid][1] = grid[3 * idx + 1];
        s_z[tid][2] = grid[3 * idx + 2];
    }
    __syncthreads();

    const u64 ZXF = pk2(s_z[2 * lane][0],      s_z[2 * lane + 1][0]);
    const u64 ZYF = pk2(s_z[2 * lane][1],      s_z[2 * lane + 1][1]);
    const u64 ZZF = pk2(s_z[2 * lane][2],      s_z[2 * lane + 1][2]);
    const u64 ZXH = pk2(s_z[64 + 2 * lane][0], s_z[65 + 2 * lane][0]);
    const u64 ZYH = pk2(s_z[64 + 2 * lane][1], s_z[65 + 2 * lane][1]);
    const u64 ZZH = pk2(s_z[64 + 2 * lane][2], s_z[65 + 2 * lane][2]);

    bv0 = NEG_INF; bv1 = NEG_INF; bv2 = NEG_INF; bv3 = NEG_INF;
    bi0 = 0; bi1 = 0; bi2 = 0; bi3 = 0;

    // ------------- pass 2: masked argmax (|dot(z,g)| < 0.2) -> x axis -------
    g = wid;
    for (; g + NWARP < G; g += 2 * NWARP) {
        const int g2 = g + NWARP;
        const ulonglong2 a0 = P0[g],  a1 = P1[g],  a2 = P2[g],
                         a3 = P3[g],  a4 = P4[g],  a5 = P5[g];
        const ulonglong2 b0 = P0[g2], b1 = P1[g2], b2 = P2[g2],
                         b3 = P3[g2], b4 = P4[g2], b5 = P5[g2];
        u64 sFa = sig9(F, a0, a1, a2, a3, a4.x);
        u64 sHa = sig9(H, a0, a1, a2, a3, a4.x);
        u64 dFa = dot3(ZXF, ZYF, ZZF, a4.y, a5.x, a5.y);
        u64 dHa = dot3(ZXH, ZYH, ZZH, a4.y, a5.x, a5.y);
        u64 sFb = sig9(F, b0, b1, b2, b3, b4.x);
        u64 sHb = sig9(H, b0, b1, b2, b3, b4.x);
        u64 dFb = dot3(ZXF, ZYF, ZZF, b4.y, b5.x, b5.y);
        u64 dHb = dot3(ZXH, ZYH, ZZH, b4.y, b5.x, b5.y);
        amaxm(sFa, dFa, g,  bv0, bi0, bv1, bi1);
        amaxm(sHa, dHa, g,  bv2, bi2, bv3, bi3);
        amaxm(sFb, dFb, g2, bv0, bi0, bv1, bi1);
        amaxm(sHb, dHb, g2, bv2, bi2, bv3, bi3);
    }
    if (g < G) {
        const ulonglong2 a0 = P0[g], a1 = P1[g], a2 = P2[g],
                         a3 = P3[g], a4 = P4[g], a5 = P5[g];
        u64 sFa = sig9(F, a0, a1, a2, a3, a4.x);
        u64 sHa = sig9(H, a0, a1, a2, a3, a4.x);
        u64 dFa = dot3(ZXF, ZYF, ZZF, a4.y, a5.x, a5.y);
        u64 dHa = dot3(ZXH, ZYH, ZZH, a4.y, a5.x, a5.y);
        amaxm(sFa, dFa, g, bv0, bi0, bv1, bi1);
        amaxm(sHa, dHa, g, bv2, bi2, bv3, bi3);
    }

    s_pv[wid][2 * lane]      = bv0; s_pidx[wid][2 * lane]      = bi0;
    s_pv[wid][2 * lane + 1]  = bv1; s_pidx[wid][2 * lane + 1]  = bi1;
    s_pv[wid][64 + 2 * lane] = bv2; s_pidx[wid][64 + 2 * lane] = bi2;
    s_pv[wid][65 + 2 * lane] = bv3; s_pidx[wid][65 + 2 * lane] = bi3;
    __syncthreads();

    // ------------------------ per-row epilogue ------------------------------
    if (tid < RPB) {
        int row = rowbase + tid;
        if (row < B) {
            float v = s_pv[0][tid]; int idx = s_pidx[0][tid];
#pragma unroll
            for (int w = 1; w < NWARP; w++) {
                float ov = s_pv[w][tid]; int oi = s_pidx[w][tid];
                if (ov > v || (ov == v && oi < idx)) { v = ov; idx = oi; }
            }
            float xr0 = grid[3 * idx + 0], xr1 = grid[3 * idx + 1], xr2 = grid[3 * idx + 2];
            float zr0 = s_z[tid][0], zr1 = s_z[tid][1], zr2 = s_z[tid][2];
            float zn = sqrtf(zr0 * zr0 + zr1 * zr1 + zr2 * zr2);
            float zinv = 1.0f / fmaxf(zn, 1e-12f);
            float z0 = zr0 * zinv, z1 = zr1 * zinv, z2 = zr2 * zinv;
            float pr = xr0 * z0 + xr1 * z1 + xr2 * z2;
            float x0 = xr0 - pr * z0, x1 = xr1 - pr * z1, x2 = xr2 - pr * z2;
            float xn = sqrtf(x0 * x0 + x1 * x1 + x2 * x2);
            float xinv = 1.0f / fmaxf(xn, 1e-12f);
            x0 *= xinv; x1 *= xinv; x2 *= xinv;
            float y0 = z1 * x2 - z2 * x1;
            float y1 = z2 * x0 - z0 * x2;
            float y2 = z0 * x1 - z1 * x0;
            float m00 = x0, m01 = y0, m02 = z0;
            float m10 = x1, m11 = y1, m12 = z1;
            float m20 = x2, m21 = y2, m22 = z2;
            float qa0 = sqrtf(fmaxf(1.0f + m00 + m11 + m22, 0.0f));
            float qa1 = sqrtf(fmaxf(1.0f + m00 - m11 - m22, 0.0f));
            float qa2 = sqrtf(fmaxf(1.0f - m00 + m11 - m22, 0.0f));
            float qa3 = sqrtf(fmaxf(1.0f - m00 - m11 + m22, 0.0f));
            float c0[4] = {qa0 * qa0, m21 - m12, m02 - m20, m10 - m01};
            float c1[4] = {m21 - m12, qa1 * qa1, m10 + m01, m02 + m20};
            float c2[4] = {m02 - m20, m10 + m01, qa2 * qa2, m12 + m21};
            float c3[4] = {m10 - m01, m20 + m02, m21 + m12, qa3 * qa3};
            int best = 0; float bq = qa0;
            if (qa1 > bq) { bq = qa1; best = 1; }
            if (qa2 > bq) { bq = qa2; best = 2; }
            if (qa3 > bq) { bq = qa3; best = 3; }
            const float* cr = (best == 0) ? c0 : (best == 1) ? c1 : (best == 2) ? c2 : c3;
            float dn = 2.0f * fmaxf(bq, 0.1f);
            out[row * 4 + 0] = cr[0] / dn;
            out[row * 4 + 1] = cr[1] / dn;
            out[row * 4 + 2] = cr[2] / dn;
            out[row * 4 + 3] = cr[3] / dn;
            out[4 * B + row] = f0[row] * 57.29577951308232f;
        }
    }
}

extern "C" void kernel_launch(void* const* d_in, const int* in_sizes, int n_in,
                              void* d_out, int out_size) {
    const float* f0 = (const float*)d_in[0];
    const float* f4 = (const float*)d_in[2];
    const float* grid = (const float*)d_in[4];
    int B = in_sizes[0];          // f0: [B,1]
    int G = in_sizes[4] / 3;      // grid_vecs: [G,3]
    if (G > GMAX) G = GMAX;

    sh_precompute_kernel<<<(G + 255) / 256, 256>>>(grid, G);

    int blocks = (B + RPB - 1) / RPB;
    decoder_kernel<<<blocks, BLOCK>>>(f0, f4, grid, (float*)d_out, B, G);
}

// round 4
// speedup vs baseline: 2.6704x; 2.6704x over previous
#include <cuda_runtime.h>
#include <math.h>
#include <stdint.h>

typedef unsigned long long u64;

#define GMAX 10240
#define PMAX (GMAX / 2)
#define NW 8
#define BLOCK 256
#define RPB 64
#define CHP 128   // g-pairs per smem chunk

// g-pair packed tables (no duplication):
// T1 (pass 1): v[0..8] = {Yi[g0], Yi[g1]} pairs, v[9] = pad      -> 80 B
// T2 (pass 2): v[0..8] = Y pairs, v[9]=gx pair, v[10]=gy, v[11]=gz -> 96 B
struct __align__(16) T1e { u64 v[10]; };
struct __align__(16) T2e { u64 v[12]; };
__device__ T1e g_T1[PMAX];
__device__ T2e g_T2[PMAX];

__device__ __forceinline__ u64 dup2(float f) {
    u64 r; asm("mov.b64 %0, {%1, %1};" : "=l"(r) : "f"(f)); return r;
}
__device__ __forceinline__ u64 pk2(float lo, float hi) {
    u64 r; asm("mov.b64 %0, {%1, %2};" : "=l"(r) : "f"(lo), "f"(hi)); return r;
}
__device__ __forceinline__ void upk2(u64 v, float& lo, float& hi) {
    asm("mov.b64 {%0, %1}, %2;" : "=f"(lo), "=f"(hi) : "l"(v));
}
__device__ __forceinline__ u64 fma2(u64 a, u64 b, u64 c) {
    u64 r; asm("fma.rn.f32x2 %0, %1, %2, %3;" : "=l"(r) : "l"(a), "l"(b), "l"(c)); return r;
}
__device__ __forceinline__ u64 mul2(u64 a, u64 b) {
    u64 r; asm("mul.rn.f32x2 %0, %1, %2;" : "=l"(r) : "l"(a), "l"(b)); return r;
}

// 9-term SH dot, SINGLE sequential chain per f32x2 half — exact R1 rounding
// order (verified rel_err 4.8e-8). DO NOT re-associate.
__device__ __forceinline__ u64 sig9p(const u64* C, ulonglong2 q0, ulonglong2 q1,
                                     ulonglong2 q2, ulonglong2 q3, u64 y8) {
    u64 acc = mul2(C[0], q0.x);
    acc = fma2(C[1], q0.y, acc);
    acc = fma2(C[2], q1.x, acc);
    acc = fma2(C[3], q1.y, acc);
    acc = fma2(C[4], q2.x, acc);
    acc = fma2(C[5], q2.y, acc);
    acc = fma2(C[6], q3.x, acc);
    acc = fma2(C[7], q3.y, acc);
    acc = fma2(C[8], y8, acc);
    return acc;
}
__device__ __forceinline__ u64 dot3p(u64 zx, u64 zy, u64 zz, u64 gx, u64 gy, u64 gz) {
    u64 d = mul2(zx, gx);
    d = fma2(zy, gy, d);
    return fma2(zz, gz, d);
}
// lower-g half checked first -> first-index tie-break preserved (strict >)
__device__ __forceinline__ void amax2(u64 s, int g0, float& bv, int& bi) {
    float lo, hi; upk2(s, lo, hi);
    if (lo > bv) { bv = lo; bi = g0; }
    if (hi > bv) { bv = hi; bi = g0 + 1; }
}
__device__ __forceinline__ void amaxm2(u64 s, u64 d, int g0, float& bv, int& bi) {
    float lo, hi, dl, dh; upk2(s, lo, hi); upk2(d, dl, dh);
    if (fabsf(dl) < 0.2f && lo > bv) { bv = lo; bi = g0; }
    if (fabsf(dh) < 0.2f && hi > bv) { bv = hi; bi = g0 + 1; }
}

__device__ __forceinline__ void shY(const float* __restrict__ grid, int g,
                                    float* Y, float* gv) {
    float gx = grid[3 * g + 0], gy = grid[3 * g + 1], gz = grid[3 * g + 2];
    gv[0] = gx; gv[1] = gy; gv[2] = gz;
    float n = sqrtf(gx * gx + gy * gy + gz * gz);
    float inv = 1.0f / fmaxf(n, 1e-12f);
    float x = gx * inv, y = gy * inv, z = gz * inv;
    float x2 = x * x, y2 = y * y, z2 = z * z;
    Y[0] = 2.5033429417967046f * (x * y * (x2 - y2));
    Y[1] = 1.7701307697799304f * (y * z * (3.0f * x2 - y2));
    Y[2] = 0.9461746957575601f * (x * y * (7.0f * z2 - 1.0f));
    Y[3] = 0.6690465435572892f * (y * z * (7.0f * z2 - 3.0f));
    Y[4] = 0.10578554691520431f * (35.0f * z2 * z2 - 30.0f * z2 + 3.0f);
    Y[5] = 0.6690465435572892f * (x * z * (7.0f * z2 - 3.0f));
    Y[6] = 0.47308734787878004f * ((x2 - y2) * (7.0f * z2 - 1.0f));
    Y[7] = 1.7701307697799304f * (x * z * (x2 - y2));
    Y[8] = 0.6258357354491761f * (x2 * x2 - 6.0f * x2 * y2 + y2 * y2);
}

__global__ void sh_precompute(const float* __restrict__ grid, int G, int P) {
    int p = blockIdx.x * blockDim.x + threadIdx.x;
    if (p >= P) return;
    int g0 = 2 * p;
    int g1 = min(2 * p + 1, G - 1);   // odd-G pad = copy of last (tie-break safe)
    float Ya[9], Yb[9], ga[3], gb[3];
    shY(grid, g0, Ya, ga);
    shY(grid, g1, Yb, gb);
    T1e t1; T2e t2;
#pragma unroll
    for (int i = 0; i < 9; i++) {
        u64 pr = pk2(Ya[i], Yb[i]);
        t1.v[i] = pr; t2.v[i] = pr;
    }
    t1.v[9] = 0;
    t2.v[9]  = pk2(ga[0], gb[0]);
    t2.v[10] = pk2(ga[1], gb[1]);
    t2.v[11] = pk2(ga[2], gb[2]);
    g_T1[p] = t1;
    g_T2[p] = t2;
}

__device__ __forceinline__ void stage16(const char* gsrc, uint32_t sdst, int bytes, int tid) {
    for (int i = tid * 16; i < bytes; i += BLOCK * 16)
        asm volatile("cp.async.cg.shared.global [%0], [%1], 16;"
                     :: "r"(sdst + (uint32_t)i), "l"(gsrc + i));
}
#define CPA_COMMIT() asm volatile("cp.async.commit_group;" ::: "memory")
#define CPA_WAIT1()  asm volatile("cp.async.wait_group 1;" ::: "memory")

// ---------------------------------------------------------------------------
// 256 threads = 8 warps; 64 rows/block (2 rows per lane, scalar per row);
// f32x2 packs (g, g+1). Warps split the pair range of each staged chunk.
// Double-buffered cp.async staging hides L2 latency.
// ---------------------------------------------------------------------------
__global__ __launch_bounds__(BLOCK, 2) void decoder_kernel(
    const float* __restrict__ f0,
    const float* __restrict__ f4,
    const float* __restrict__ grid,
    float* __restrict__ out,
    int B, int G)
{
    __shared__ __align__(16) char sbuf[2][CHP * 96];
    __shared__ float s_pv[NW][RPB];
    __shared__ int s_pidx[NW][RPB];
    __shared__ float s_z[RPB][3];

    const int tid = threadIdx.x;
    const int lane = tid & 31;
    const int wid = tid >> 5;
    const int rowbase = blockIdx.x * RPB;
    const float NEG_INF = __int_as_float(0xff800000);

    const int rA = rowbase + lane;        // row for chain A
    const int rB = rA + 32;               // row for chain B

    u64 FA[9], FB[9];
#pragma unroll
    for (int i = 0; i < 9; i++) {
        FA[i] = dup2((rA < B) ? f4[rA * 9 + i] : 0.0f);
        FB[i] = dup2((rB < B) ? f4[rB * 9 + i] : 0.0f);
    }

    const int P = (G + 1) / 2;
    const int nch = (P + CHP - 1) / CHP;
    uint32_t sb[2];
    sb[0] = (uint32_t)__cvta_generic_to_shared(sbuf[0]);
    sb[1] = (uint32_t)__cvta_generic_to_shared(sbuf[1]);

    float bvA = NEG_INF, bvB = NEG_INF;
    int biA = 0, biB = 0;

    // ----------------------------- pass 1 ----------------------------------
    stage16((const char*)g_T1, sb[0], min(CHP, P) * 80, tid);
    CPA_COMMIT();
    for (int c = 0; c < nch; c++) {
        int nxt = c + 1;
        if (nxt < nch)
            stage16((const char*)(g_T1 + nxt * CHP), sb[nxt & 1],
                    min(CHP, P - nxt * CHP) * 80, tid);
        CPA_COMMIT();
        CPA_WAIT1();
        __syncthreads();
        const char* buf = sbuf[c & 1];
        const int cnt = min(CHP, P - c * CHP);
        const int gb = c * CHP * 2;
        for (int k = wid; k < cnt; k += NW) {
            const ulonglong2* e = (const ulonglong2*)(buf + k * 80);
            ulonglong2 q0 = e[0], q1 = e[1], q2 = e[2], q3 = e[3], q4 = e[4];
            u64 aA = sig9p(FA, q0, q1, q2, q3, q4.x);
            u64 aB = sig9p(FB, q0, q1, q2, q3, q4.x);
            int g0 = gb + 2 * k;
            amax2(aA, g0, bvA, biA);
            amax2(aB, g0, bvB, biB);
        }
        __syncthreads();
    }

    s_pv[wid][lane] = bvA;      s_pidx[wid][lane] = biA;
    s_pv[wid][lane + 32] = bvB; s_pidx[wid][lane + 32] = biB;
    __syncthreads();
    if (tid < RPB) {
        float v = s_pv[0][tid]; int idx = s_pidx[0][tid];
#pragma unroll
        for (int w = 1; w < NW; w++) {
            float ov = s_pv[w][tid]; int oi = s_pidx[w][tid];
            if (ov > v || (ov == v && oi < idx)) { v = ov; idx = oi; }
        }
        s_z[tid][0] = grid[3 * idx + 0];
        s_z[tid][1] = grid[3 * idx + 1];
        s_z[tid][2] = grid[3 * idx + 2];
    }
    __syncthreads();

    const u64 ZAx = dup2(s_z[lane][0]),      ZAy = dup2(s_z[lane][1]),      ZAz = dup2(s_z[lane][2]);
    const u64 ZBx = dup2(s_z[lane + 32][0]), ZBy = dup2(s_z[lane + 32][1]), ZBz = dup2(s_z[lane + 32][2]);

    bvA = NEG_INF; bvB = NEG_INF; biA = 0; biB = 0;

    // ----------------------------- pass 2 ----------------------------------
    stage16((const char*)g_T2, sb[0], min(CHP, P) * 96, tid);
    CPA_COMMIT();
    for (int c = 0; c < nch; c++) {
        int nxt = c + 1;
        if (nxt < nch)
            stage16((const char*)(g_T2 + nxt * CHP), sb[nxt & 1],
                    min(CHP, P - nxt * CHP) * 96, tid);
        CPA_COMMIT();
        CPA_WAIT1();
        __syncthreads();
        const char* buf = sbuf[c & 1];
        const int cnt = min(CHP, P - c * CHP);
        const int gb = c * CHP * 2;
        for (int k = wid; k < cnt; k += NW) {
            const ulonglong2* e = (const ulonglong2*)(buf + k * 96);
            ulonglong2 q0 = e[0], q1 = e[1], q2 = e[2], q3 = e[3], q4 = e[4], q5 = e[5];
            u64 aA = sig9p(FA, q0, q1, q2, q3, q4.x);
            u64 aB = sig9p(FB, q0, q1, q2, q3, q4.x);
            u64 dA = dot3p(ZAx, ZAy, ZAz, q4.y, q5.x, q5.y);
            u64 dB = dot3p(ZBx, ZBy, ZBz, q4.y, q5.x, q5.y);
            int g0 = gb + 2 * k;
            amaxm2(aA, dA, g0, bvA, biA);
            amaxm2(aB, dB, g0, bvB, biB);
        }
        __syncthreads();
    }

    s_pv[wid][lane] = bvA;      s_pidx[wid][lane] = biA;
    s_pv[wid][lane + 32] = bvB; s_pidx[wid][lane + 32] = biB;
    __syncthreads();

    // ----------------------------- epilogue --------------------------------
    if (tid < RPB) {
        int row = rowbase + tid;
        if (row < B) {
            float v = s_pv[0][tid]; int idx = s_pidx[0][tid];
#pragma unroll
            for (int w = 1; w < NW; w++) {
                float ov = s_pv[w][tid]; int oi = s_pidx[w][tid];
                if (ov > v || (ov == v && oi < idx)) { v = ov; idx = oi; }
            }
            float xr0 = grid[3 * idx + 0], xr1 = grid[3 * idx + 1], xr2 = grid[3 * idx + 2];
            float zr0 = s_z[tid][0], zr1 = s_z[tid][1], zr2 = s_z[tid][2];
            float zn = sqrtf(zr0 * zr0 + zr1 * zr1 + zr2 * zr2);
            float zinv = 1.0f / fmaxf(zn, 1e-12f);
            float z0 = zr0 * zinv, z1 = zr1 * zinv, z2 = zr2 * zinv;
            float pr = xr0 * z0 + xr1 * z1 + xr2 * z2;
            float x0 = xr0 - pr * z0, x1 = xr1 - pr * z1, x2 = xr2 - pr * z2;
            float xn = sqrtf(x0 * x0 + x1 * x1 + x2 * x2);
            float xinv = 1.0f / fmaxf(xn, 1e-12f);
            x0 *= xinv; x1 *= xinv; x2 *= xinv;
            float y0 = z1 * x2 - z2 * x1;
            float y1 = z2 * x0 - z0 * x2;
            float y2 = z0 * x1 - z1 * x0;
            float m00 = x0, m01 = y0, m02 = z0;
            float m10 = x1, m11 = y1, m12 = z1;
            float m20 = x2, m21 = y2, m22 = z2;
            float qa0 = sqrtf(fmaxf(1.0f + m00 + m11 + m22, 0.0f));
            float qa1 = sqrtf(fmaxf(1.0f + m00 - m11 - m22, 0.0f));
            float qa2 = sqrtf(fmaxf(1.0f - m00 + m11 - m22, 0.0f));
            float qa3 = sqrtf(fmaxf(1.0f - m00 - m11 + m22, 0.0f));
            float c0[4] = {qa0 * qa0, m21 - m12, m02 - m20, m10 - m01};
            float c1[4] = {m21 - m12, qa1 * qa1, m10 + m01, m02 + m20};
            float c2[4] = {m02 - m20, m10 + m01, qa2 * qa2, m12 + m21};
            float c3[4] = {m10 - m01, m20 + m02, m21 + m12, qa3 * qa3};
            int best = 0; float bq = qa0;
            if (qa1 > bq) { bq = qa1; best = 1; }
            if (qa2 > bq) { bq = qa2; best = 2; }
            if (qa3 > bq) { bq = qa3; best = 3; }
            const float* cr = (best == 0) ? c0 : (best == 1) ? c1 : (best == 2) ? c2 : c3;
            float dn = 2.0f * fmaxf(bq, 0.1f);
            out[row * 4 + 0] = cr[0] / dn;
            out[row * 4 + 1] = cr[1] / dn;
            out[row * 4 + 2] = cr[2] / dn;
            out[row * 4 + 3] = cr[3] / dn;
            out[4 * B + row] = f0[row] * 57.29577951308232f;
        }
    }
}

extern "C" void kernel_launch(void* const* d_in, const int* in_sizes, int n_in,
                              void* d_out, int out_size) {
    const float* f0 = (const float*)d_in[0];
    const float* f4 = (const float*)d_in[2];
    const float* grid = (const float*)d_in[4];
    int B = in_sizes[0];          // f0: [B,1]
    int G = in_sizes[4] / 3;      // grid_vecs: [G,3]
    if (G > GMAX) G = GMAX;
    int P = (G + 1) / 2;

    sh_precompute<<<(P + 255) / 256, 256>>>(grid, G, P);

    int blocks = (B + RPB - 1) / RPB;
    decoder_kernel<<<blocks, BLOCK>>>(f0, f4, grid, (float*)d_out, B, G);
}

// round 5
// speedup vs baseline: 2.7387x; 1.0256x over previous
#include <cuda_runtime.h>
#include <math.h>
#include <stdint.h>

typedef unsigned long long u64;

#define GMAX 10240
#define PMAX (GMAX / 2)
#define NW 8
#define BLOCK 256
#define RPB 64
#define CHP 192   // g-pairs per smem chunk (2*192*96 = 36KB < 48KB static cap)

// g-pair packed tables (no duplication):
// T1 (pass 1): v[0..8] = {Yi[g0], Yi[g1]} pairs, v[9] = pad      -> 80 B
// T2 (pass 2): v[0..8] = Y pairs, v[9]=gx pair, v[10]=gy, v[11]=gz -> 96 B
struct __align__(16) T1e { u64 v[10]; };
struct __align__(16) T2e { u64 v[12]; };
__device__ T1e g_T1[PMAX];
__device__ T2e g_T2[PMAX];

__device__ __forceinline__ u64 dup2(float f) {
    u64 r; asm("mov.b64 %0, {%1, %1};" : "=l"(r) : "f"(f)); return r;
}
__device__ __forceinline__ u64 pk2(float lo, float hi) {
    u64 r; asm("mov.b64 %0, {%1, %2};" : "=l"(r) : "f"(lo), "f"(hi)); return r;
}
__device__ __forceinline__ void upk2(u64 v, float& lo, float& hi) {
    asm("mov.b64 {%0, %1}, %2;" : "=f"(lo), "=f"(hi) : "l"(v));
}
__device__ __forceinline__ u64 fma2(u64 a, u64 b, u64 c) {
    u64 r; asm("fma.rn.f32x2 %0, %1, %2, %3;" : "=l"(r) : "l"(a), "l"(b), "l"(c)); return r;
}
__device__ __forceinline__ u64 mul2(u64 a, u64 b) {
    u64 r; asm("mul.rn.f32x2 %0, %1, %2;" : "=l"(r) : "l"(a), "l"(b)); return r;
}

// 9-term SH dot, SINGLE sequential chain per f32x2 half — exact R1 rounding
// order (verified rel_err 4.8e-8). DO NOT re-associate.
__device__ __forceinline__ u64 sig9p(const u64* C, ulonglong2 q0, ulonglong2 q1,
                                     ulonglong2 q2, ulonglong2 q3, u64 y8) {
    u64 acc = mul2(C[0], q0.x);
    acc = fma2(C[1], q0.y, acc);
    acc = fma2(C[2], q1.x, acc);
    acc = fma2(C[3], q1.y, acc);
    acc = fma2(C[4], q2.x, acc);
    acc = fma2(C[5], q2.y, acc);
    acc = fma2(C[6], q3.x, acc);
    acc = fma2(C[7], q3.y, acc);
    acc = fma2(C[8], y8, acc);
    return acc;
}
__device__ __forceinline__ u64 dot3p(u64 zx, u64 zy, u64 zz, u64 gx, u64 gy, u64 gz) {
    u64 d = mul2(zx, gx);
    d = fma2(zy, gy, d);
    return fma2(zz, gz, d);
}
// lower-g half checked first -> first-index tie-break preserved (strict >)
__device__ __forceinline__ void amax2(u64 s, int g0, float& bv, int& bi) {
    float lo, hi; upk2(s, lo, hi);
    if (lo > bv) { bv = lo; bi = g0; }
    if (hi > bv) { bv = hi; bi = g0 + 1; }
}
__device__ __forceinline__ void amaxm2(u64 s, u64 d, int g0, float& bv, int& bi) {
    float lo, hi, dl, dh; upk2(s, lo, hi); upk2(d, dl, dh);
    if (fabsf(dl) < 0.2f && lo > bv) { bv = lo; bi = g0; }
    if (fabsf(dh) < 0.2f && hi > bv) { bv = hi; bi = g0 + 1; }
}

__device__ __forceinline__ void shY(const float* __restrict__ grid, int g,
                                    float* Y, float* gv) {
    float gx = grid[3 * g + 0], gy = grid[3 * g + 1], gz = grid[3 * g + 2];
    gv[0] = gx; gv[1] = gy; gv[2] = gz;
    float n = sqrtf(gx * gx + gy * gy + gz * gz);
    float inv = 1.0f / fmaxf(n, 1e-12f);
    float x = gx * inv, y = gy * inv, z = gz * inv;
    float x2 = x * x, y2 = y * y, z2 = z * z;
    Y[0] = 2.5033429417967046f * (x * y * (x2 - y2));
    Y[1] = 1.7701307697799304f * (y * z * (3.0f * x2 - y2));
    Y[2] = 0.9461746957575601f * (x * y * (7.0f * z2 - 1.0f));
    Y[3] = 0.6690465435572892f * (y * z * (7.0f * z2 - 3.0f));
    Y[4] = 0.10578554691520431f * (35.0f * z2 * z2 - 30.0f * z2 + 3.0f);
    Y[5] = 0.6690465435572892f * (x * z * (7.0f * z2 - 3.0f));
    Y[6] = 0.47308734787878004f * ((x2 - y2) * (7.0f * z2 - 1.0f));
    Y[7] = 1.7701307697799304f * (x * z * (x2 - y2));
    Y[8] = 0.6258357354491761f * (x2 * x2 - 6.0f * x2 * y2 + y2 * y2);
}

__global__ void sh_precompute(const float* __restrict__ grid, int G, int P) {
    int p = blockIdx.x * blockDim.x + threadIdx.x;
    if (p >= P) return;
    int g0 = 2 * p;
    int g1 = min(2 * p + 1, G - 1);   // odd-G pad = copy of last (tie-break safe)
    float Ya[9], Yb[9], ga[3], gb[3];
    shY(grid, g0, Ya, ga);
    shY(grid, g1, Yb, gb);
    T1e t1; T2e t2;
#pragma unroll
    for (int i = 0; i < 9; i++) {
        u64 pr = pk2(Ya[i], Yb[i]);
        t1.v[i] = pr; t2.v[i] = pr;
    }
    t1.v[9] = 0;
    t2.v[9]  = pk2(ga[0], gb[0]);
    t2.v[10] = pk2(ga[1], gb[1]);
    t2.v[11] = pk2(ga[2], gb[2]);
    g_T1[p] = t1;
    g_T2[p] = t2;
}

__device__ __forceinline__ void stage16(const char* gsrc, uint32_t sdst, int bytes, int tid) {
    for (int i = tid * 16; i < bytes; i += BLOCK * 16)
        asm volatile("cp.async.cg.shared.global [%0], [%1], 16;"
                     :: "r"(sdst + (uint32_t)i), "l"(gsrc + i));
}
#define CPA_COMMIT() asm volatile("cp.async.commit_group;" ::: "memory")
#define CPA_WAIT1()  asm volatile("cp.async.wait_group 1;" ::: "memory")

// ---------------------------------------------------------------------------
// 256 threads = 8 warps; 64 rows/block (2 rows per lane); f32x2 packs (g,g+1).
// Warps split the pair range of each staged chunk. Double-buffered cp.async.
// Pass-1 inner loop unrolled x2: 10 batched LDS.128, then 36 indep FFMA2.
// ---------------------------------------------------------------------------
__global__ __launch_bounds__(BLOCK, 2) void decoder_kernel(
    const float* __restrict__ f0,
    const float* __restrict__ f4,
    const float* __restrict__ grid,
    float* __restrict__ out,
    int B, int G)
{
    __shared__ __align__(16) char sbuf[2][CHP * 96];
    __shared__ float s_pv[NW][RPB];
    __shared__ int s_pidx[NW][RPB];
    __shared__ float s_z[RPB][3];

    const int tid = threadIdx.x;
    const int lane = tid & 31;
    const int wid = tid >> 5;
    const int rowbase = blockIdx.x * RPB;
    const float NEG_INF = __int_as_float(0xff800000);

    const int rA = rowbase + lane;        // row for chain A
    const int rB = rA + 32;               // row for chain B

    u64 FA[9], FB[9];
#pragma unroll
    for (int i = 0; i < 9; i++) {
        FA[i] = dup2((rA < B) ? f4[rA * 9 + i] : 0.0f);
        FB[i] = dup2((rB < B) ? f4[rB * 9 + i] : 0.0f);
    }

    const int P = (G + 1) / 2;
    const int nch = (P + CHP - 1) / CHP;
    uint32_t sb[2];
    sb[0] = (uint32_t)__cvta_generic_to_shared(sbuf[0]);
    sb[1] = (uint32_t)__cvta_generic_to_shared(sbuf[1]);

    float bvA = NEG_INF, bvB = NEG_INF;
    int biA = 0, biB = 0;

    // ----------------------------- pass 1 ----------------------------------
    stage16((const char*)g_T1, sb[0], min(CHP, P) * 80, tid);
    CPA_COMMIT();
    for (int c = 0; c < nch; c++) {
        int nxt = c + 1;
        if (nxt < nch)
            stage16((const char*)(g_T1 + nxt * CHP), sb[nxt & 1],
                    min(CHP, P - nxt * CHP) * 80, tid);
        CPA_COMMIT();
        CPA_WAIT1();
        __syncthreads();
        const char* buf = sbuf[c & 1];
        const int cnt = min(CHP, P - c * CHP);
        const int gb = c * CHP * 2;
        int k = wid;
        for (; k + NW < cnt; k += 2 * NW) {
            const ulonglong2* e1 = (const ulonglong2*)(buf + k * 80);
            const ulonglong2* e2 = (const ulonglong2*)(buf + (k + NW) * 80);
            ulonglong2 a0 = e1[0], a1 = e1[1], a2 = e1[2], a3 = e1[3], a4 = e1[4];
            ulonglong2 b0 = e2[0], b1 = e2[1], b2 = e2[2], b3 = e2[3], b4 = e2[4];
            u64 sAa = sig9p(FA, a0, a1, a2, a3, a4.x);
            u64 sBa = sig9p(FB, a0, a1, a2, a3, a4.x);
            u64 sAb = sig9p(FA, b0, b1, b2, b3, b4.x);
            u64 sBb = sig9p(FB, b0, b1, b2, b3, b4.x);
            int g0 = gb + 2 * k;
            amax2(sAa, g0, bvA, biA);
            amax2(sBa, g0, bvB, biB);
            amax2(sAb, g0 + 2 * NW, bvA, biA);
            amax2(sBb, g0 + 2 * NW, bvB, biB);
        }
        if (k < cnt) {
            const ulonglong2* e = (const ulonglong2*)(buf + k * 80);
            ulonglong2 q0 = e[0], q1 = e[1], q2 = e[2], q3 = e[3], q4 = e[4];
            u64 aA = sig9p(FA, q0, q1, q2, q3, q4.x);
            u64 aB = sig9p(FB, q0, q1, q2, q3, q4.x);
            int g0 = gb + 2 * k;
            amax2(aA, g0, bvA, biA);
            amax2(aB, g0, bvB, biB);
        }
        __syncthreads();
    }

    s_pv[wid][lane] = bvA;      s_pidx[wid][lane] = biA;
    s_pv[wid][lane + 32] = bvB; s_pidx[wid][lane + 32] = biB;
    __syncthreads();
    if (tid < RPB) {
        float v = s_pv[0][tid]; int idx = s_pidx[0][tid];
#pragma unroll
        for (int w = 1; w < NW; w++) {
            float ov = s_pv[w][tid]; int oi = s_pidx[w][tid];
            if (ov > v || (ov == v && oi < idx)) { v = ov; idx = oi; }
        }
        s_z[tid][0] = grid[3 * idx + 0];
        s_z[tid][1] = grid[3 * idx + 1];
        s_z[tid][2] = grid[3 * idx + 2];
    }
    __syncthreads();

    const u64 ZAx = dup2(s_z[lane][0]),      ZAy = dup2(s_z[lane][1]),      ZAz = dup2(s_z[lane][2]);
    const u64 ZBx = dup2(s_z[lane + 32][0]), ZBy = dup2(s_z[lane + 32][1]), ZBz = dup2(s_z[lane + 32][2]);

    bvA = NEG_INF; bvB = NEG_INF; biA = 0; biB = 0;

    // ----------------------------- pass 2 ----------------------------------
    stage16((const char*)g_T2, sb[0], min(CHP, P) * 96, tid);
    CPA_COMMIT();
    for (int c = 0; c < nch; c++) {
        int nxt = c + 1;
        if (nxt < nch)
            stage16((const char*)(g_T2 + nxt * CHP), sb[nxt & 1],
                    min(CHP, P - nxt * CHP) * 96, tid);
        CPA_COMMIT();
        CPA_WAIT1();
        __syncthreads();
        const char* buf = sbuf[c & 1];
        const int cnt = min(CHP, P - c * CHP);
        const int gb = c * CHP * 2;
        for (int k = wid; k < cnt; k += NW) {
            const ulonglong2* e = (const ulonglong2*)(buf + k * 96);
            ulonglong2 q0 = e[0], q1 = e[1], q2 = e[2], q3 = e[3], q4 = e[4], q5 = e[5];
            u64 aA = sig9p(FA, q0, q1, q2, q3, q4.x);
            u64 aB = sig9p(FB, q0, q1, q2, q3, q4.x);
            u64 dA = dot3p(ZAx, ZAy, ZAz, q4.y, q5.x, q5.y);
            u64 dB = dot3p(ZBx, ZBy, ZBz, q4.y, q5.x, q5.y);
            int g0 = gb + 2 * k;
            amaxm2(aA, dA, g0, bvA, biA);
            amaxm2(aB, dB, g0, bvB, biB);
        }
        __syncthreads();
    }

    s_pv[wid][lane] = bvA;      s_pidx[wid][lane] = biA;
    s_pv[wid][lane + 32] = bvB; s_pidx[wid][lane + 32] = biB;
    __syncthreads();

    // ----------------------------- epilogue --------------------------------
    if (tid < RPB) {
        int row = rowbase + tid;
        if (row < B) {
            float v = s_pv[0][tid]; int idx = s_pidx[0][tid];
#pragma unroll
            for (int w = 1; w < NW; w++) {
                float ov = s_pv[w][tid]; int oi = s_pidx[w][tid];
                if (ov > v || (ov == v && oi < idx)) { v = ov; idx = oi; }
            }
            float xr0 = grid[3 * idx + 0], xr1 = grid[3 * idx + 1], xr2 = grid[3 * idx + 2];
            float zr0 = s_z[tid][0], zr1 = s_z[tid][1], zr2 = s_z[tid][2];
            float zn = sqrtf(zr0 * zr0 + zr1 * zr1 + zr2 * zr2);
            float zinv = 1.0f / fmaxf(zn, 1e-12f);
            float z0 = zr0 * zinv, z1 = zr1 * zinv, z2 = zr2 * zinv;
            float pr = xr0 * z0 + xr1 * z1 + xr2 * z2;
            float x0 = xr0 - pr * z0, x1 = xr1 - pr * z1, x2 = xr2 - pr * z2;
            float xn = sqrtf(x0 * x0 + x1 * x1 + x2 * x2);
            float xinv = 1.0f / fmaxf(xn, 1e-12f);
            x0 *= xinv; x1 *= xinv; x2 *= xinv;
            float y0 = z1 * x2 - z2 * x1;
            float y1 = z2 * x0 - z0 * x2;
            float y2 = z0 * x1 - z1 * x0;
            float m00 = x0, m01 = y0, m02 = z0;
            float m10 = x1, m11 = y1, m12 = z1;
            float m20 = x2, m21 = y2, m22 = z2;
            float qa0 = sqrtf(fmaxf(1.0f + m00 + m11 + m22, 0.0f));
            float qa1 = sqrtf(fmaxf(1.0f + m00 - m11 - m22, 0.0f));
            float qa2 = sqrtf(fmaxf(1.0f - m00 + m11 - m22, 0.0f));
            float qa3 = sqrtf(fmaxf(1.0f - m00 - m11 + m22, 0.0f));
            float c0[4] = {qa0 * qa0, m21 - m12, m02 - m20, m10 - m01};
            float c1[4] = {m21 - m12, qa1 * qa1, m10 + m01, m02 + m20};
            float c2[4] = {m02 - m20, m10 + m01, qa2 * qa2, m12 + m21};
            float c3[4] = {m10 - m01, m20 + m02, m21 + m12, qa3 * qa3};
            int best = 0; float bq = qa0;
            if (qa1 > bq) { bq = qa1; best = 1; }
            if (qa2 > bq) { bq = qa2; best = 2; }
            if (qa3 > bq) { bq = qa3; best = 3; }
            const float* cr = (best == 0) ? c0 : (best == 1) ? c1 : (best == 2) ? c2 : c3;
            float dn = 2.0f * fmaxf(bq, 0.1f);
            out[row * 4 + 0] = cr[0] / dn;
            out[row * 4 + 1] = cr[1] / dn;
            out[row * 4 + 2] = cr[2] / dn;
            out[row * 4 + 3] = cr[3] / dn;
            out[4 * B + row] = f0[row] * 57.29577951308232f;
        }
    }
}

extern "C" void kernel_launch(void* const* d_in, const int* in_sizes, int n_in,
                              void* d_out, int out_size) {
    const float* f0 = (const float*)d_in[0];
    const float* f4 = (const float*)d_in[2];
    const float* grid = (const float*)d_in[4];
    int B = in_sizes[0];          // f0: [B,1]
    int G = in_sizes[4] / 3;      // grid_vecs: [G,3]
    if (G > GMAX) G = GMAX;
    int P = (G + 1) / 2;

    sh_precompute<<<(P + 255) / 256, 256>>>(grid, G, P);

    int blocks = (B + RPB - 1) / RPB;
    decoder_kernel<<<blocks, BLOCK>>>(f0, f4, grid, (float*)d_out, B, G);
}